// round 16
// baseline (speedup 1.0000x reference)
#include <cuda_runtime.h>
#include <cuda_bf16.h>
#include <math.h>

#define BB 32
#define TT 2048
#define NN 2048
#define DD 512
#define LL 256
#define TEE 1024
#define HH 8
#define SPLITS 16
#define SB 72    // attn smem stride (el)
#define SAG 24   // gemm A smem stride (el), 16 k-cols + 8 pad
#define SBW 136  // gemm B smem stride (el), 128 cols + 8 pad
#define ASTG (128 * SAG)
#define BSTG (16 * SBW)

#define CP_ASYNC16(dst, src) \
    asm volatile("cp.async.cg.shared.global [%0], [%1], 16;" \
                 :: "r"((unsigned)__cvta_generic_to_shared(dst)), "l"(src))
#define CP_COMMIT asm volatile("cp.async.commit_group;")
#define CP_WAIT0  asm volatile("cp.async.wait_group 0;" ::: "memory")

// ---------------- scratch ----------------
__device__ float g_kv[(size_t)BB * NN * 1024];   // k|v interleaved per row
__device__ float g_q[(size_t)BB * TT * DD];
__device__ float g_act[(size_t)BB * TT * DD];
__device__ float g_pm[BB * SPLITS * DD];
__device__ float g_ps[BB * SPLITS * DD];
__device__ float g_m[BB * DD];
__device__ float g_z[BB * DD];
__device__ float g_attn[(size_t)BB * HH * 4096];
__device__ float g_attn_p[4 * (size_t)BB * HH * 4096];
__device__ float g_ss[BB * 2 * DD];
__device__ float g_muf[BB * NN], g_rsf[BB * NN];
__device__ float g_mux[BB * TT], g_rsx[BB * TT];
__device__ __align__(16) __nv_bfloat16 g_wkv_h[256 * 1024];
__device__ __align__(16) __nv_bfloat16 g_wkv_l[256 * 1024];
__device__ __align__(16) __nv_bfloat16 g_wq_h[512 * 512];
__device__ __align__(16) __nv_bfloat16 g_wq_l[512 * 512];
__device__ __align__(16) __nv_bfloat16 g_wo_h[512 * 512];
__device__ __align__(16) __nv_bfloat16 g_wo_l[512 * 512];
__device__ float g_bkv[1024];

__device__ __forceinline__ void bsplit(float v, __nv_bfloat16& h, __nv_bfloat16& l) {
    h = __float2bfloat16(v);
    l = __float2bfloat16(v - __bfloat162float(h));
}

__device__ __forceinline__ void mma_bf16(float c[4], const unsigned a[4], unsigned b0, unsigned b1) {
    asm volatile(
        "mma.sync.aligned.m16n8k16.row.col.f32.bf16.bf16.f32 "
        "{%0,%1,%2,%3},{%4,%5,%6,%7},{%8,%9},{%0,%1,%2,%3};\n"
        : "+f"(c[0]), "+f"(c[1]), "+f"(c[2]), "+f"(c[3])
        : "r"(a[0]), "r"(a[1]), "r"(a[2]), "r"(a[3]), "r"(b0), "r"(b1));
}
__device__ __forceinline__ void ldsm4(unsigned r[4], const __nv_bfloat16* p) {
    unsigned a = (unsigned)__cvta_generic_to_shared(p);
    asm volatile("ldmatrix.sync.aligned.m8n8.x4.shared.b16 {%0,%1,%2,%3}, [%4];"
                 : "=r"(r[0]), "=r"(r[1]), "=r"(r[2]), "=r"(r[3]) : "r"(a));
}
__device__ __forceinline__ void ldsm4t(unsigned r[4], const __nv_bfloat16* p) {
    unsigned a = (unsigned)__cvta_generic_to_shared(p);
    asm volatile("ldmatrix.sync.aligned.m8n8.x4.trans.shared.b16 {%0,%1,%2,%3}, [%4];"
                 : "=r"(r[0]), "=r"(r[1]), "=r"(r[2]), "=r"(r[3]) : "r"(a));
}

// 32x32 warp tile triple-mma accumulate (proven round 10)
__device__ __forceinline__ void mma_block(float acc[2][4][4], unsigned ah[2][4], unsigned al[2][4],
                                          unsigned b4h[2][4], unsigned b4l[2][4]) {
    #pragma unroll
    for (int mi = 0; mi < 2; mi++)
        #pragma unroll
        for (int ni = 0; ni < 4; ni++) {
            unsigned bh0 = b4h[ni >> 1][(ni & 1) * 2], bh1 = b4h[ni >> 1][(ni & 1) * 2 + 1];
            unsigned bl0 = b4l[ni >> 1][(ni & 1) * 2], bl1 = b4l[ni >> 1][(ni & 1) * 2 + 1];
            mma_bf16(acc[mi][ni], ah[mi], bh0, bh1);
            mma_bf16(acc[mi][ni], ah[mi], bl0, bl1);
            mma_bf16(acc[mi][ni], al[mi], bh0, bh1);
        }
}

// ---------------- emb scale/shift ----------------
__global__ void k_emb(const float* __restrict__ emb, const float* __restrict__ We,
                      const float* __restrict__ be) {
    int b = blockIdx.x;
    __shared__ float se[TEE];
    int tid = threadIdx.x;
    for (int i = tid; i < TEE; i += 512) {
        float e = emb[b * TEE + i];
        se[i] = e / (1.f + __expf(-e));
    }
    __syncthreads();
    for (int o = tid; o < 2 * DD; o += 512) {
        float acc = be[o];
        #pragma unroll 4
        for (int i = 0; i < TEE; i++) acc += se[i] * We[i * (2 * DD) + o];
        g_ss[b * 2 * DD + o] = acc;
    }
}

// ---------------- weight split ----------------
__global__ void k_cvtW(const float* __restrict__ Wk, const float* __restrict__ Wv,
                       const float* __restrict__ Wq, const float* __restrict__ Wo,
                       const float* __restrict__ bk, const float* __restrict__ bv) {
    int i = blockIdx.x * 256 + threadIdx.x;
    __nv_bfloat16 h, l;
    if (blockIdx.y == 0) {
        int k = i >> 10, n = i & 1023;
        float w = (n < 512) ? Wk[k * 512 + n] : Wv[k * 512 + n - 512];
        bsplit(w, h, l);
        g_wkv_h[i] = h; g_wkv_l[i] = l;
        if (i < 1024) g_bkv[i] = (i < 512) ? bk[i] : bv[i - 512];
    } else if (blockIdx.y == 1) {
        bsplit(Wq[i], h, l);
        g_wq_h[i] = h; g_wq_l[i] = l;
    } else {
        bsplit(Wo[i], h, l);
        g_wo_h[i] = h; g_wo_l[i] = l;
    }
}

// ---------------- LN row stats ----------------
__global__ void k_stats(const float* __restrict__ in, int len, int which) {
    int row = blockIdx.x * 8 + (threadIdx.x >> 5);
    int lane = threadIdx.x & 31;
    const float* p = in + (size_t)row * len;
    float s = 0.f, s2 = 0.f;
    for (int j = lane; j < len; j += 32) { float v = p[j]; s += v; s2 += v * v; }
    #pragma unroll
    for (int o = 16; o; o >>= 1) {
        s += __shfl_xor_sync(0xffffffffu, s, o);
        s2 += __shfl_xor_sync(0xffffffffu, s2, o);
    }
    if (lane == 0) {
        float m = s / len;
        float rs = rsqrtf(s2 / len - m * m + 1e-5f);
        if (which) { g_mux[row] = m; g_rsx[row] = rs; }
        else       { g_muf[row] = m; g_rsf[row] = rs; }
    }
}

// ---------------- pipelined split-bf16 tensor GEMM (128x128 tile, 16 warps, double buffer, 2 CTA/SM) ----------------
// SEL 0: kv (A=xf+LN, K=256, N=1024)  1: q (A=x+LN, K=512, N=512)  2: o (A=g_act, +x residual)
template<int SEL>
__global__ void __launch_bounds__(512, 2)
k_gemm6(const float* __restrict__ Ap, const float* __restrict__ lg_, const float* __restrict__ lb_,
        const float* __restrict__ biasp, const float* __restrict__ xres, float* __restrict__ Cout) {
    constexpr int KF = (SEL == 0) ? 256 : 512;
    constexpr int NB = (SEL == 0) ? 1024 : 512;
    constexpr int NST = KF / 16;
    const float* A = (SEL == 2) ? g_act : Ap;
    const __nv_bfloat16* Bh = (SEL == 0) ? g_wkv_h : ((SEL == 1) ? g_wq_h : g_wo_h);
    const __nv_bfloat16* Bl = (SEL == 0) ? g_wkv_l : ((SEL == 1) ? g_wq_l : g_wo_l);
    const float* bias = (SEL == 0) ? g_bkv : biasp;
    const float* mu = (SEL == 0) ? g_muf : g_mux;
    const float* rsd = (SEL == 0) ? g_rsf : g_rsx;
    float* C = (SEL == 0) ? g_kv : ((SEL == 1) ? g_q : Cout);

    __shared__ __align__(16) __nv_bfloat16 sAh[2 * ASTG], sAl[2 * ASTG];
    __shared__ __align__(16) __nv_bfloat16 sBh[2 * BSTG], sBl[2 * BSTG];
    int tid = threadIdx.x, wid = tid >> 5, lane = tid & 31;
    int wm = wid & 3, wn = wid >> 2;          // 4 m-warps x 4 n-warps, 32x32 each
    int lg = lane & 7, mat = lane >> 3;
    int g = lane >> 2, t4 = lane & 3;
    int row0 = blockIdx.y * 128, col0 = blockIdx.x * 128;

    // per-thread fixed fill coordinates
    int bu = tid & 255;
    int brow = bu >> 4, bcol = (bu & 15) * 8;
    const __nv_bfloat16* Bsrc = (tid < 256) ? Bh : Bl;
    __nv_bfloat16* sBdst = (tid < 256) ? sBh : sBl;

    float acc[2][4][4];
    #pragma unroll
    for (int mi = 0; mi < 2; mi++)
        #pragma unroll
        for (int ni = 0; ni < 4; ni++)
            #pragma unroll
            for (int q = 0; q < 4; q++) acc[mi][ni][q] = 0.f;

    // ---- prologue: fill stage for kt=0 into buf 0 ----
    #pragma unroll
    for (int i = 0; i < 4; i++) {
        int idx = i * 512 + tid;
        int r = idx >> 4, c = idx & 15;
        float v = A[(size_t)(row0 + r) * KF + c];
        if (SEL < 2) v = (v - mu[row0 + r]) * rsd[row0 + r] * lg_[c] + lb_[c];
        __nv_bfloat16 h, l;
        bsplit(v, h, l);
        sAh[r * SAG + c] = h; sAl[r * SAG + c] = l;
    }
    CP_ASYNC16(sBdst + brow * SBW + bcol, Bsrc + (size_t)brow * NB + col0 + bcol);
    CP_COMMIT;
    CP_WAIT0;
    __syncthreads();

    int buf = 0;
    #pragma unroll 2
    for (int st = 0; st < NST; st++) {
        bool nxt = (st + 1 < NST);
        int ktn = (st + 1) * 16;
        float ar[4];
        if (nxt) {
            // prefetch next A tile into registers (latency hidden by mma below)
            #pragma unroll
            for (int i = 0; i < 4; i++) {
                int idx = i * 512 + tid;
                int r = idx >> 4, c = idx & 15;
                ar[i] = A[(size_t)(row0 + r) * KF + ktn + c];
            }
            // cp.async next B tile into alternate buffer
            CP_ASYNC16(sBdst + (buf ^ 1) * BSTG + brow * SBW + bcol,
                       Bsrc + (size_t)(ktn + brow) * NB + col0 + bcol);
            CP_COMMIT;
        }
        // ---- mma on current buffer ----
        {
            const __nv_bfloat16* pAh = sAh + buf * ASTG;
            const __nv_bfloat16* pAl = sAl + buf * ASTG;
            const __nv_bfloat16* pBh = sBh + buf * BSTG;
            const __nv_bfloat16* pBl = sBl + buf * BSTG;
            unsigned ah[2][4], al[2][4], b4h[2][4], b4l[2][4];
            #pragma unroll
            for (int mi = 0; mi < 2; mi++) {
                int row = wm * 32 + mi * 16 + ((mat & 1) << 3) + lg;
                int col = (mat >> 1) << 3;
                ldsm4(ah[mi], pAh + row * SAG + col);
                ldsm4(al[mi], pAl + row * SAG + col);
            }
            #pragma unroll
            for (int p = 0; p < 2; p++) {
                int row = ((mat & 1) << 3) + lg;
                int col = wn * 32 + p * 16 + ((mat >> 1) << 3);
                ldsm4t(b4h[p], pBh + row * SBW + col);
                ldsm4t(b4l[p], pBl + row * SBW + col);
            }
            mma_block(acc, ah, al, b4h, b4l);
        }
        if (nxt) {
            // convert prefetched A regs into alternate buffer
            #pragma unroll
            for (int i = 0; i < 4; i++) {
                int idx = i * 512 + tid;
                int r = idx >> 4, c = idx & 15;
                float v = ar[i];
                if (SEL < 2) v = (v - mu[row0 + r]) * rsd[row0 + r] * lg_[ktn + c] + lb_[ktn + c];
                __nv_bfloat16 h, l;
                bsplit(v, h, l);
                sAh[(buf ^ 1) * ASTG + r * SAG + c] = h;
                sAl[(buf ^ 1) * ASTG + r * SAG + c] = l;
            }
            CP_WAIT0;
        }
        __syncthreads();
        buf ^= 1;
    }
    #pragma unroll
    for (int mi = 0; mi < 2; mi++) {
        int r0 = row0 + wm * 32 + mi * 16 + g;
        #pragma unroll
        for (int ni = 0; ni < 4; ni++) {
            int c = col0 + wn * 32 + ni * 8 + t4 * 2;
            float b0 = bias[c], b1 = bias[c + 1];
            float v0 = acc[mi][ni][0] + b0, v1 = acc[mi][ni][1] + b1;
            float v2 = acc[mi][ni][2] + b0, v3 = acc[mi][ni][3] + b1;
            size_t o0 = (size_t)r0 * NB + c, o1 = (size_t)(r0 + 8) * NB + c;
            if (SEL == 2) {
                v0 += xres[o0]; v1 += xres[o0 + 1];
                v2 += xres[o1]; v3 += xres[o1 + 1];
            }
            *(float2*)(C + o0) = make_float2(v0, v1);
            *(float2*)(C + o1) = make_float2(v2, v3);
        }
    }
}

// ---------------- k softmax stats over n ----------------
__global__ void k_redk() {
    int b = blockIdx.x, sp = blockIdx.y, d = threadIdx.x;
    size_t base = ((size_t)b * NN + sp * (NN / SPLITS)) * 1024 + d;
    float m = -1e30f, s = 0.f;
    for (int n = 0; n < NN / SPLITS; n++) {
        float v = g_kv[base + (size_t)n * 1024];
        if (v > m) { s = s * __expf(m - v) + 1.f; m = v; }
        else s += __expf(v - m);
    }
    g_pm[(b * SPLITS + sp) * DD + d] = m;
    g_ps[(b * SPLITS + sp) * DD + d] = s;
}

__global__ void k_comb() {
    int b = blockIdx.x, d = threadIdx.x;
    float m = -1e30f;
    for (int sp = 0; sp < SPLITS; sp++) m = fmaxf(m, g_pm[(b * SPLITS + sp) * DD + d]);
    float z = 0.f;
    for (int sp = 0; sp < SPLITS; sp++)
        z += g_ps[(b * SPLITS + sp) * DD + d] * __expf(g_pm[(b * SPLITS + sp) * DD + d] - m);
    g_m[b * DD + d] = m;
    g_z[b * DD + d] = z;
}

// ---------------- attn partials: exp(k-m)^T @ v via ldmatrix mma ----------------
__global__ void __launch_bounds__(128)
k_attn2() {
    int bh = blockIdx.x, ch = blockIdx.y;
    int b = bh >> 3, h = bh & 7;
    __shared__ __align__(16) __nv_bfloat16 sEh[32 * SB], sEl[32 * SB];
    __shared__ __align__(16) __nv_bfloat16 sVh[32 * SB], sVl[32 * SB];
    __shared__ float smv[64];
    int tid = threadIdx.x, wid = tid >> 5, lane = tid & 31;
    int wm = wid & 1, wn = wid >> 1;
    int lg = lane & 7, mat = lane >> 3;
    int g = lane >> 2, t = lane & 3;
    if (tid < 64) smv[tid] = g_m[b * DD + h * 64 + tid];
    __syncthreads();

    float acc[2][4][4];
    #pragma unroll
    for (int mi = 0; mi < 2; mi++)
        #pragma unroll
        for (int ni = 0; ni < 4; ni++)
            #pragma unroll
            for (int q = 0; q < 4; q++) acc[mi][ni][q] = 0.f;

    for (int kt = 0; kt < 512; kt += 32) {
        #pragma unroll
        for (int i = 0; i < 16; i++) {
            int idx = i * 128 + tid;
            int n = idx >> 6, dd = idx & 63;
            size_t base = ((size_t)b * NN + ch * 512 + kt + n) * 1024 + h * 64 + dd;
            __nv_bfloat16 hh, ll;
            bsplit(__expf(g_kv[base] - smv[dd]), hh, ll);
            sEh[n * SB + dd] = hh; sEl[n * SB + dd] = ll;
            bsplit(g_kv[base + 512], hh, ll);
            sVh[n * SB + dd] = hh; sVl[n * SB + dd] = ll;
        }
        __syncthreads();
        #pragma unroll
        for (int ks = 0; ks < 32; ks += 16) {
            unsigned ah[2][4], al[2][4], b4h[2][4], b4l[2][4];
            #pragma unroll
            for (int mi = 0; mi < 2; mi++) {
                int row = ks + ((mat >> 1) << 3) + lg;
                int col = wm * 32 + mi * 16 + ((mat & 1) << 3);
                ldsm4t(ah[mi], sEh + row * SB + col);
                ldsm4t(al[mi], sEl + row * SB + col);
            }
            #pragma unroll
            for (int p = 0; p < 2; p++) {
                int row = ks + ((mat & 1) << 3) + lg;
                int col = wn * 32 + p * 16 + ((mat >> 1) << 3);
                ldsm4t(b4h[p], sVh + row * SB + col);
                ldsm4t(b4l[p], sVl + row * SB + col);
            }
            mma_block(acc, ah, al, b4h, b4l);
        }
        __syncthreads();
    }
    float* outp = g_attn_p + ((size_t)ch * (BB * HH) + bh) * 4096;
    #pragma unroll
    for (int mi = 0; mi < 2; mi++) {
        int r = wm * 32 + mi * 16 + g;
        #pragma unroll
        for (int ni = 0; ni < 4; ni++) {
            int c = wn * 32 + ni * 8 + t * 2;
            *(float2*)(outp + r * 64 + c) = make_float2(acc[mi][ni][0], acc[mi][ni][1]);
            *(float2*)(outp + (r + 8) * 64 + c) = make_float2(acc[mi][ni][2], acc[mi][ni][3]);
        }
    }
}

__global__ void k_ascale() {
    int bh = blockIdx.x;
    int b = bh >> 3, h = bh & 7;
    for (int i = threadIdx.x; i < 4096; i += 256) {
        int dd = i >> 6;
        float s = g_attn_p[(size_t)bh * 4096 + i]
                + g_attn_p[((size_t)(BB * HH) + bh) * 4096 + i]
                + g_attn_p[((size_t)(2 * BB * HH) + bh) * 4096 + i]
                + g_attn_p[((size_t)(3 * BB * HH) + bh) * 4096 + i];
        g_attn[(size_t)bh * 4096 + i] = s / g_z[b * DD + h * 64 + dd];
    }
}

// ---------------- softmax(q) + y + LN(y) + modulate + silu ----------------
__global__ void __launch_bounds__(512, 2)
k_smy(const float* __restrict__ sg, const float* __restrict__ sb) {
    int blk = blockIdx.x;
    int b = blk / (TT / 8);
    int t0 = (blk % (TT / 8)) * 8;
    __shared__ float sq[8][DD], sa[8][DD];
    __shared__ float red[2][8][64];
    __shared__ float smean[8], srstd[8];
    __shared__ float gmax[64], gsum[64], pred[64][8];
    int tid = threadIdx.x, d = tid;
    size_t rowbase = ((size_t)b * TT + t0) * DD;
    #pragma unroll
    for (int rr = 0; rr < 8; rr++) sq[rr][d] = g_q[rowbase + (size_t)rr * DD + d];
    __syncthreads();
    {
        int gq = tid >> 3, kk = tid & 7;
        int rr = gq >> 3, hh2 = gq & 7;
        float m = -1e30f;
        for (int j = kk; j < 64; j += 8) m = fmaxf(m, sq[rr][hh2 * 64 + j]);
        pred[gq][kk] = m;
        __syncthreads();
        if (kk == 0) {
            float mm = pred[gq][0];
            #pragma unroll
            for (int i = 1; i < 8; i++) mm = fmaxf(mm, pred[gq][i]);
            gmax[gq] = mm;
        }
        __syncthreads();
        float mm = gmax[gq], ss = 0.f;
        for (int j = kk; j < 64; j += 8) ss += __expf(sq[rr][hh2 * 64 + j] - mm);
        pred[gq][kk] = ss;
        __syncthreads();
        if (kk == 0) {
            float tsum = 0.f;
            #pragma unroll
            for (int i = 0; i < 8; i++) tsum += pred[gq][i];
            gsum[gq] = tsum;
        }
        __syncthreads();
    }
    int hh = d >> 6;
    #pragma unroll
    for (int rr = 0; rr < 8; rr++) {
        int gq = rr * 8 + hh;
        sq[rr][d] = __expf(sq[rr][d] - gmax[gq]) / gsum[gq];
    }
    __syncthreads();
    float ay[8];
    {
        int l = d & 63;
        const float* ap = g_attn + (size_t)(b * HH + hh) * 4096 + l;
        #pragma unroll
        for (int rr = 0; rr < 8; rr++) ay[rr] = 0.f;
        #pragma unroll 4
        for (int dd = 0; dd < 64; dd++) {
            float a = ap[dd * 64];
            #pragma unroll
            for (int rr = 0; rr < 8; rr++) ay[rr] += sq[rr][hh * 64 + dd] * a;
        }
        #pragma unroll
        for (int rr = 0; rr < 8; rr++) sa[rr][d] = ay[rr];
    }
    __syncthreads();
    int r = tid >> 6, lane = tid & 63;
    {
        float s = 0.f, s2 = 0.f;
        for (int j = lane; j < DD; j += 64) { float v = sa[r][j]; s += v; s2 += v * v; }
        red[0][r][lane] = s; red[1][r][lane] = s2;
        __syncthreads();
        for (int off = 32; off > 0; off >>= 1) {
            if (lane < off) {
                red[0][r][lane] += red[0][r][lane + off];
                red[1][r][lane] += red[1][r][lane + off];
            }
            __syncthreads();
        }
        if (tid < 8) {
            float m = red[0][tid][0] / DD;
            smean[tid] = m; srstd[tid] = rsqrtf(red[1][tid][0] / DD - m * m + 1e-5f);
        }
        __syncthreads();
    }
    {
        float sgd = sg[d], sbd = sb[d];
        float sc = 1.f + g_ss[b * 2 * DD + d];
        float sh = g_ss[b * 2 * DD + DD + d];
        #pragma unroll
        for (int rr = 0; rr < 8; rr++) {
            float hv = (ay[rr] - smean[rr]) * srstd[rr] * sgd + sbd;
            hv = hv * sc + sh;
            g_act[rowbase + (size_t)rr * DD + d] = hv / (1.f + __expf(-hv));
        }
    }
}

extern "C" void kernel_launch(void* const* d_in, const int* in_sizes, int n_in,
                              void* d_out, int out_size) {
    const float* x   = (const float*)d_in[0];
    const float* xf  = (const float*)d_in[1];
    const float* emb = (const float*)d_in[2];
    const float* ng  = (const float*)d_in[3];
    const float* nb  = (const float*)d_in[4];
    const float* tg  = (const float*)d_in[5];
    const float* tb  = (const float*)d_in[6];
    const float* Wq  = (const float*)d_in[7];
    const float* bq  = (const float*)d_in[8];
    const float* Wk  = (const float*)d_in[9];
    const float* bk  = (const float*)d_in[10];
    const float* Wv  = (const float*)d_in[11];
    const float* bv  = (const float*)d_in[12];
    const float* We  = (const float*)d_in[13];
    const float* be  = (const float*)d_in[14];
    const float* sg  = (const float*)d_in[15];
    const float* sb  = (const float*)d_in[16];
    const float* Wo  = (const float*)d_in[17];
    const float* bo  = (const float*)d_in[18];
    float* out = (float*)d_out;

    k_emb<<<BB, 512>>>(emb, We, be);
    k_cvtW<<<dim3(1024, 3), 256>>>(Wk, Wv, Wq, Wo, bk, bv);
    k_stats<<<BB * NN / 8, 256>>>(xf, LL, 0);
    k_gemm6<0><<<dim3(8, BB * NN / 128), 512>>>(xf, tg, tb, nullptr, nullptr, nullptr);
    k_redk<<<dim3(BB, SPLITS), DD>>>();
    k_comb<<<BB, DD>>>();
    k_stats<<<BB * TT / 8, 256>>>(x, DD, 1);
    k_gemm6<1><<<dim3(4, BB * TT / 128), 512>>>(x, ng, nb, bq, nullptr, nullptr);
    k_attn2<<<dim3(BB * HH, 4), 128>>>();
    k_ascale<<<BB * HH, 256>>>();
    k_smy<<<BB * TT / 8, 512>>>(sg, sb);
    k_gemm6<2><<<dim3(4, BB * TT / 128), 512>>>(nullptr, nullptr, nullptr, bo, x, out);
}

// round 17
// speedup vs baseline: 1.3743x; 1.3743x over previous
#include <cuda_runtime.h>
#include <cuda_bf16.h>
#include <math.h>

#define BB 32
#define TT 2048
#define NN 2048
#define DD 512
#define LL 256
#define TEE 1024
#define HH 8
#define SPLITS 16
#define SB 72    // attn smem stride (el)
#define SAG 24   // gemm A smem stride (el), 16 k-cols + 8 pad
#define SBW 136  // gemm B smem stride (el), 128 cols + 8 pad
#define ASTG (64 * SAG)
#define BSTG (16 * SBW)

#define CP_ASYNC16(dst, src) \
    asm volatile("cp.async.cg.shared.global [%0], [%1], 16;" \
                 :: "r"((unsigned)__cvta_generic_to_shared(dst)), "l"(src))
#define CP_COMMIT asm volatile("cp.async.commit_group;")
#define CP_WAIT0  asm volatile("cp.async.wait_group 0;" ::: "memory")

// ---------------- scratch ----------------
__device__ float g_kv[(size_t)BB * NN * 1024];   // k|v interleaved per row
__device__ float g_q[(size_t)BB * TT * DD];
__device__ float g_act[(size_t)BB * TT * DD];
__device__ float g_pm[BB * SPLITS * DD];
__device__ float g_ps[BB * SPLITS * DD];
__device__ float g_m[BB * DD];
__device__ float g_z[BB * DD];
__device__ float g_attn[(size_t)BB * HH * 4096];
__device__ float g_attn_p[4 * (size_t)BB * HH * 4096];
__device__ float g_ss[BB * 2 * DD];
__device__ float g_muf[BB * NN], g_rsf[BB * NN];
__device__ float g_mux[BB * TT], g_rsx[BB * TT];
__device__ __align__(16) __nv_bfloat16 g_wkv_h[256 * 1024];
__device__ __align__(16) __nv_bfloat16 g_wkv_l[256 * 1024];
__device__ __align__(16) __nv_bfloat16 g_wq_h[512 * 512];
__device__ __align__(16) __nv_bfloat16 g_wq_l[512 * 512];
__device__ __align__(16) __nv_bfloat16 g_wo_h[512 * 512];
__device__ __align__(16) __nv_bfloat16 g_wo_l[512 * 512];
__device__ float g_bkv[1024];

__device__ __forceinline__ void bsplit(float v, __nv_bfloat16& h, __nv_bfloat16& l) {
    h = __float2bfloat16(v);
    l = __float2bfloat16(v - __bfloat162float(h));
}

__device__ __forceinline__ void mma_bf16(float c[4], const unsigned a[4], unsigned b0, unsigned b1) {
    asm volatile(
        "mma.sync.aligned.m16n8k16.row.col.f32.bf16.bf16.f32 "
        "{%0,%1,%2,%3},{%4,%5,%6,%7},{%8,%9},{%0,%1,%2,%3};\n"
        : "+f"(c[0]), "+f"(c[1]), "+f"(c[2]), "+f"(c[3])
        : "r"(a[0]), "r"(a[1]), "r"(a[2]), "r"(a[3]), "r"(b0), "r"(b1));
}
__device__ __forceinline__ void ldsm4(unsigned r[4], const __nv_bfloat16* p) {
    unsigned a = (unsigned)__cvta_generic_to_shared(p);
    asm volatile("ldmatrix.sync.aligned.m8n8.x4.shared.b16 {%0,%1,%2,%3}, [%4];"
                 : "=r"(r[0]), "=r"(r[1]), "=r"(r[2]), "=r"(r[3]) : "r"(a));
}
__device__ __forceinline__ void ldsm4t(unsigned r[4], const __nv_bfloat16* p) {
    unsigned a = (unsigned)__cvta_generic_to_shared(p);
    asm volatile("ldmatrix.sync.aligned.m8n8.x4.trans.shared.b16 {%0,%1,%2,%3}, [%4];"
                 : "=r"(r[0]), "=r"(r[1]), "=r"(r[2]), "=r"(r[3]) : "r"(a));
}

// 32x32 warp tile triple-mma accumulate (proven round 10)
__device__ __forceinline__ void mma_block(float acc[2][4][4], unsigned ah[2][4], unsigned al[2][4],
                                          unsigned b4h[2][4], unsigned b4l[2][4]) {
    #pragma unroll
    for (int mi = 0; mi < 2; mi++)
        #pragma unroll
        for (int ni = 0; ni < 4; ni++) {
            unsigned bh0 = b4h[ni >> 1][(ni & 1) * 2], bh1 = b4h[ni >> 1][(ni & 1) * 2 + 1];
            unsigned bl0 = b4l[ni >> 1][(ni & 1) * 2], bl1 = b4l[ni >> 1][(ni & 1) * 2 + 1];
            mma_bf16(acc[mi][ni], ah[mi], bh0, bh1);
            mma_bf16(acc[mi][ni], ah[mi], bl0, bl1);
            mma_bf16(acc[mi][ni], al[mi], bh0, bh1);
        }
}

// ---------------- emb scale/shift ----------------
__global__ void k_emb(const float* __restrict__ emb, const float* __restrict__ We,
                      const float* __restrict__ be) {
    int b = blockIdx.x;
    __shared__ float se[TEE];
    int tid = threadIdx.x;
    for (int i = tid; i < TEE; i += 512) {
        float e = emb[b * TEE + i];
        se[i] = e / (1.f + __expf(-e));
    }
    __syncthreads();
    for (int o = tid; o < 2 * DD; o += 512) {
        float acc = be[o];
        #pragma unroll 4
        for (int i = 0; i < TEE; i++) acc += se[i] * We[i * (2 * DD) + o];
        g_ss[b * 2 * DD + o] = acc;
    }
}

// ---------------- weight split ----------------
__global__ void k_cvtW(const float* __restrict__ Wk, const float* __restrict__ Wv,
                       const float* __restrict__ Wq, const float* __restrict__ Wo,
                       const float* __restrict__ bk, const float* __restrict__ bv) {
    int i = blockIdx.x * 256 + threadIdx.x;
    __nv_bfloat16 h, l;
    if (blockIdx.y == 0) {
        int k = i >> 10, n = i & 1023;
        float w = (n < 512) ? Wk[k * 512 + n] : Wv[k * 512 + n - 512];
        bsplit(w, h, l);
        g_wkv_h[i] = h; g_wkv_l[i] = l;
        if (i < 1024) g_bkv[i] = (i < 512) ? bk[i] : bv[i - 512];
    } else if (blockIdx.y == 1) {
        bsplit(Wq[i], h, l);
        g_wq_h[i] = h; g_wq_l[i] = l;
    } else {
        bsplit(Wo[i], h, l);
        g_wo_h[i] = h; g_wo_l[i] = l;
    }
}

// ---------------- LN row stats ----------------
__global__ void k_stats(const float* __restrict__ in, int len, int which) {
    int row = blockIdx.x * 8 + (threadIdx.x >> 5);
    int lane = threadIdx.x & 31;
    const float* p = in + (size_t)row * len;
    float s = 0.f, s2 = 0.f;
    for (int j = lane; j < len; j += 32) { float v = p[j]; s += v; s2 += v * v; }
    #pragma unroll
    for (int o = 16; o; o >>= 1) {
        s += __shfl_xor_sync(0xffffffffu, s, o);
        s2 += __shfl_xor_sync(0xffffffffu, s2, o);
    }
    if (lane == 0) {
        float m = s / len;
        float rs = rsqrtf(s2 / len - m * m + 1e-5f);
        if (which) { g_mux[row] = m; g_rsx[row] = rs; }
        else       { g_muf[row] = m; g_rsf[row] = rs; }
    }
}

// ---------------- pipelined split-bf16 tensor GEMM (64x128 tile, 8 warps, double buffer, 3 CTA/SM) ----------------
// SEL 0: kv (A=xf+LN, K=256, N=1024)  1: q (A=x+LN, K=512, N=512)  2: o (A=g_act, +x residual)
template<int SEL>
__global__ void __launch_bounds__(256, 3)
k_gemm7(const float* __restrict__ Ap, const float* __restrict__ lg_, const float* __restrict__ lb_,
        const float* __restrict__ biasp, const float* __restrict__ xres, float* __restrict__ Cout) {
    constexpr int KF = (SEL == 0) ? 256 : 512;
    constexpr int NB = (SEL == 0) ? 1024 : 512;
    constexpr int NST = KF / 16;
    const float* A = (SEL == 2) ? g_act : Ap;
    const __nv_bfloat16* Bh = (SEL == 0) ? g_wkv_h : ((SEL == 1) ? g_wq_h : g_wo_h);
    const __nv_bfloat16* Bl = (SEL == 0) ? g_wkv_l : ((SEL == 1) ? g_wq_l : g_wo_l);
    const float* bias = (SEL == 0) ? g_bkv : biasp;
    const float* mu = (SEL == 0) ? g_muf : g_mux;
    const float* rsd = (SEL == 0) ? g_rsf : g_rsx;
    float* C = (SEL == 0) ? g_kv : ((SEL == 1) ? g_q : Cout);

    __shared__ __align__(16) __nv_bfloat16 sAh[2 * ASTG], sAl[2 * ASTG];
    __shared__ __align__(16) __nv_bfloat16 sBh[2 * BSTG], sBl[2 * BSTG];
    int tid = threadIdx.x, wid = tid >> 5, lane = tid & 31;
    int wm = wid & 1, wn = wid >> 1;          // 2 m-warps x 4 n-warps, 32x32 each
    int lg = lane & 7, mat = lane >> 3;
    int g = lane >> 2, t4 = lane & 3;
    int row0 = blockIdx.y * 64, col0 = blockIdx.x * 128;

    // per-thread fixed B fill coordinates (16x128 tile, 16B chunks: 256 per array)
    int brow = tid >> 4, bcol = (tid & 15) * 8;

    float acc[2][4][4];
    #pragma unroll
    for (int mi = 0; mi < 2; mi++)
        #pragma unroll
        for (int ni = 0; ni < 4; ni++)
            #pragma unroll
            for (int q = 0; q < 4; q++) acc[mi][ni][q] = 0.f;

    // ---- prologue: fill stage for kt=0 into buf 0 ----
    #pragma unroll
    for (int i = 0; i < 4; i++) {
        int idx = i * 256 + tid;
        int r = idx >> 4, c = idx & 15;
        float v = A[(size_t)(row0 + r) * KF + c];
        if (SEL < 2) v = (v - mu[row0 + r]) * rsd[row0 + r] * lg_[c] + lb_[c];
        __nv_bfloat16 h, l;
        bsplit(v, h, l);
        sAh[r * SAG + c] = h; sAl[r * SAG + c] = l;
    }
    CP_ASYNC16(sBh + brow * SBW + bcol, Bh + (size_t)brow * NB + col0 + bcol);
    CP_ASYNC16(sBl + brow * SBW + bcol, Bl + (size_t)brow * NB + col0 + bcol);
    CP_COMMIT;
    CP_WAIT0;
    __syncthreads();

    int buf = 0;
    #pragma unroll 2
    for (int st = 0; st < NST; st++) {
        bool nxt = (st + 1 < NST);
        int ktn = (st + 1) * 16;
        float ar[4];
        if (nxt) {
            // prefetch next A tile into registers (latency hidden by mma below)
            #pragma unroll
            for (int i = 0; i < 4; i++) {
                int idx = i * 256 + tid;
                int r = idx >> 4, c = idx & 15;
                ar[i] = A[(size_t)(row0 + r) * KF + ktn + c];
            }
            // cp.async next B tile into alternate buffer
            CP_ASYNC16(sBh + (buf ^ 1) * BSTG + brow * SBW + bcol,
                       Bh + (size_t)(ktn + brow) * NB + col0 + bcol);
            CP_ASYNC16(sBl + (buf ^ 1) * BSTG + brow * SBW + bcol,
                       Bl + (size_t)(ktn + brow) * NB + col0 + bcol);
            CP_COMMIT;
        }
        // ---- mma on current buffer ----
        {
            const __nv_bfloat16* pAh = sAh + buf * ASTG;
            const __nv_bfloat16* pAl = sAl + buf * ASTG;
            const __nv_bfloat16* pBh = sBh + buf * BSTG;
            const __nv_bfloat16* pBl = sBl + buf * BSTG;
            unsigned ah[2][4], al[2][4], b4h[2][4], b4l[2][4];
            #pragma unroll
            for (int mi = 0; mi < 2; mi++) {
                int row = wm * 32 + mi * 16 + ((mat & 1) << 3) + lg;
                int col = (mat >> 1) << 3;
                ldsm4(ah[mi], pAh + row * SAG + col);
                ldsm4(al[mi], pAl + row * SAG + col);
            }
            #pragma unroll
            for (int p = 0; p < 2; p++) {
                int row = ((mat & 1) << 3) + lg;
                int col = wn * 32 + p * 16 + ((mat >> 1) << 3);
                ldsm4t(b4h[p], pBh + row * SBW + col);
                ldsm4t(b4l[p], pBl + row * SBW + col);
            }
            mma_block(acc, ah, al, b4h, b4l);
        }
        if (nxt) {
            // convert prefetched A regs into alternate buffer
            #pragma unroll
            for (int i = 0; i < 4; i++) {
                int idx = i * 256 + tid;
                int r = idx >> 4, c = idx & 15;
                float v = ar[i];
                if (SEL < 2) v = (v - mu[row0 + r]) * rsd[row0 + r] * lg_[ktn + c] + lb_[ktn + c];
                __nv_bfloat16 h, l;
                bsplit(v, h, l);
                sAh[(buf ^ 1) * ASTG + r * SAG + c] = h;
                sAl[(buf ^ 1) * ASTG + r * SAG + c] = l;
            }
            CP_WAIT0;
        }
        __syncthreads();
        buf ^= 1;
    }
    #pragma unroll
    for (int mi = 0; mi < 2; mi++) {
        int r0 = row0 + wm * 32 + mi * 16 + g;
        #pragma unroll
        for (int ni = 0; ni < 4; ni++) {
            int c = col0 + wn * 32 + ni * 8 + t4 * 2;
            float b0 = bias[c], b1 = bias[c + 1];
            float v0 = acc[mi][ni][0] + b0, v1 = acc[mi][ni][1] + b1;
            float v2 = acc[mi][ni][2] + b0, v3 = acc[mi][ni][3] + b1;
            size_t o0 = (size_t)r0 * NB + c, o1 = (size_t)(r0 + 8) * NB + c;
            if (SEL == 2) {
                v0 += xres[o0]; v1 += xres[o0 + 1];
                v2 += xres[o1]; v3 += xres[o1 + 1];
            }
            *(float2*)(C + o0) = make_float2(v0, v1);
            *(float2*)(C + o1) = make_float2(v2, v3);
        }
    }
}

// ---------------- k softmax stats over n ----------------
__global__ void k_redk() {
    int b = blockIdx.x, sp = blockIdx.y, d = threadIdx.x;
    size_t base = ((size_t)b * NN + sp * (NN / SPLITS)) * 1024 + d;
    float m = -1e30f, s = 0.f;
    for (int n = 0; n < NN / SPLITS; n++) {
        float v = g_kv[base + (size_t)n * 1024];
        if (v > m) { s = s * __expf(m - v) + 1.f; m = v; }
        else s += __expf(v - m);
    }
    g_pm[(b * SPLITS + sp) * DD + d] = m;
    g_ps[(b * SPLITS + sp) * DD + d] = s;
}

__global__ void k_comb() {
    int b = blockIdx.x, d = threadIdx.x;
    float m = -1e30f;
    for (int sp = 0; sp < SPLITS; sp++) m = fmaxf(m, g_pm[(b * SPLITS + sp) * DD + d]);
    float z = 0.f;
    for (int sp = 0; sp < SPLITS; sp++)
        z += g_ps[(b * SPLITS + sp) * DD + d] * __expf(g_pm[(b * SPLITS + sp) * DD + d] - m);
    g_m[b * DD + d] = m;
    g_z[b * DD + d] = z;
}

// ---------------- attn partials: exp(k-m)^T @ v via ldmatrix mma ----------------
__global__ void __launch_bounds__(128)
k_attn2() {
    int bh = blockIdx.x, ch = blockIdx.y;
    int b = bh >> 3, h = bh & 7;
    __shared__ __align__(16) __nv_bfloat16 sEh[32 * SB], sEl[32 * SB];
    __shared__ __align__(16) __nv_bfloat16 sVh[32 * SB], sVl[32 * SB];
    __shared__ float smv[64];
    int tid = threadIdx.x, wid = tid >> 5, lane = tid & 31;
    int wm = wid & 1, wn = wid >> 1;
    int lg = lane & 7, mat = lane >> 3;
    int g = lane >> 2, t = lane & 3;
    if (tid < 64) smv[tid] = g_m[b * DD + h * 64 + tid];
    __syncthreads();

    float acc[2][4][4];
    #pragma unroll
    for (int mi = 0; mi < 2; mi++)
        #pragma unroll
        for (int ni = 0; ni < 4; ni++)
            #pragma unroll
            for (int q = 0; q < 4; q++) acc[mi][ni][q] = 0.f;

    for (int kt = 0; kt < 512; kt += 32) {
        #pragma unroll
        for (int i = 0; i < 16; i++) {
            int idx = i * 128 + tid;
            int n = idx >> 6, dd = idx & 63;
            size_t base = ((size_t)b * NN + ch * 512 + kt + n) * 1024 + h * 64 + dd;
            __nv_bfloat16 hh, ll;
            bsplit(__expf(g_kv[base] - smv[dd]), hh, ll);
            sEh[n * SB + dd] = hh; sEl[n * SB + dd] = ll;
            bsplit(g_kv[base + 512], hh, ll);
            sVh[n * SB + dd] = hh; sVl[n * SB + dd] = ll;
        }
        __syncthreads();
        #pragma unroll
        for (int ks = 0; ks < 32; ks += 16) {
            unsigned ah[2][4], al[2][4], b4h[2][4], b4l[2][4];
            #pragma unroll
            for (int mi = 0; mi < 2; mi++) {
                int row = ks + ((mat >> 1) << 3) + lg;
                int col = wm * 32 + mi * 16 + ((mat & 1) << 3);
                ldsm4t(ah[mi], sEh + row * SB + col);
                ldsm4t(al[mi], sEl + row * SB + col);
            }
            #pragma unroll
            for (int p = 0; p < 2; p++) {
                int row = ks + ((mat & 1) << 3) + lg;
                int col = wn * 32 + p * 16 + ((mat >> 1) << 3);
                ldsm4t(b4h[p], sVh + row * SB + col);
                ldsm4t(b4l[p], sVl + row * SB + col);
            }
            mma_block(acc, ah, al, b4h, b4l);
        }
        __syncthreads();
    }
    float* outp = g_attn_p + ((size_t)ch * (BB * HH) + bh) * 4096;
    #pragma unroll
    for (int mi = 0; mi < 2; mi++) {
        int r = wm * 32 + mi * 16 + g;
        #pragma unroll
        for (int ni = 0; ni < 4; ni++) {
            int c = wn * 32 + ni * 8 + t * 2;
            *(float2*)(outp + r * 64 + c) = make_float2(acc[mi][ni][0], acc[mi][ni][1]);
            *(float2*)(outp + (r + 8) * 64 + c) = make_float2(acc[mi][ni][2], acc[mi][ni][3]);
        }
    }
}

__global__ void k_ascale() {
    int bh = blockIdx.x;
    int b = bh >> 3, h = bh & 7;
    for (int i = threadIdx.x; i < 4096; i += 256) {
        int dd = i >> 6;
        float s = g_attn_p[(size_t)bh * 4096 + i]
                + g_attn_p[((size_t)(BB * HH) + bh) * 4096 + i]
                + g_attn_p[((size_t)(2 * BB * HH) + bh) * 4096 + i]
                + g_attn_p[((size_t)(3 * BB * HH) + bh) * 4096 + i];
        g_attn[(size_t)bh * 4096 + i] = s / g_z[b * DD + h * 64 + dd];
    }
}

// ---------------- softmax(q) + y + LN(y) + modulate + silu ----------------
__global__ void __launch_bounds__(512, 2)
k_smy(const float* __restrict__ sg, const float* __restrict__ sb) {
    int blk = blockIdx.x;
    int b = blk / (TT / 8);
    int t0 = (blk % (TT / 8)) * 8;
    __shared__ float sq[8][DD], sa[8][DD];
    __shared__ float red[2][8][64];
    __shared__ float smean[8], srstd[8];
    __shared__ float gmax[64], gsum[64], pred[64][8];
    int tid = threadIdx.x, d = tid;
    size_t rowbase = ((size_t)b * TT + t0) * DD;
    #pragma unroll
    for (int rr = 0; rr < 8; rr++) sq[rr][d] = g_q[rowbase + (size_t)rr * DD + d];
    __syncthreads();
    {
        int gq = tid >> 3, kk = tid & 7;
        int rr = gq >> 3, hh2 = gq & 7;
        float m = -1e30f;
        for (int j = kk; j < 64; j += 8) m = fmaxf(m, sq[rr][hh2 * 64 + j]);
        pred[gq][kk] = m;
        __syncthreads();
        if (kk == 0) {
            float mm = pred[gq][0];
            #pragma unroll
            for (int i = 1; i < 8; i++) mm = fmaxf(mm, pred[gq][i]);
            gmax[gq] = mm;
        }
        __syncthreads();
        float mm = gmax[gq], ss = 0.f;
        for (int j = kk; j < 64; j += 8) ss += __expf(sq[rr][hh2 * 64 + j] - mm);
        pred[gq][kk] = ss;
        __syncthreads();
        if (kk == 0) {
            float tsum = 0.f;
            #pragma unroll
            for (int i = 0; i < 8; i++) tsum += pred[gq][i];
            gsum[gq] = tsum;
        }
        __syncthreads();
    }
    int hh = d >> 6;
    #pragma unroll
    for (int rr = 0; rr < 8; rr++) {
        int gq = rr * 8 + hh;
        sq[rr][d] = __expf(sq[rr][d] - gmax[gq]) / gsum[gq];
    }
    __syncthreads();
    float ay[8];
    {
        int l = d & 63;
        const float* ap = g_attn + (size_t)(b * HH + hh) * 4096 + l;
        #pragma unroll
        for (int rr = 0; rr < 8; rr++) ay[rr] = 0.f;
        #pragma unroll 4
        for (int dd = 0; dd < 64; dd++) {
            float a = ap[dd * 64];
            #pragma unroll
            for (int rr = 0; rr < 8; rr++) ay[rr] += sq[rr][hh * 64 + dd] * a;
        }
        #pragma unroll
        for (int rr = 0; rr < 8; rr++) sa[rr][d] = ay[rr];
    }
    __syncthreads();
    int r = tid >> 6, lane = tid & 63;
    {
        float s = 0.f, s2 = 0.f;
        for (int j = lane; j < DD; j += 64) { float v = sa[r][j]; s += v; s2 += v * v; }
        red[0][r][lane] = s; red[1][r][lane] = s2;
        __syncthreads();
        for (int off = 32; off > 0; off >>= 1) {
            if (lane < off) {
                red[0][r][lane] += red[0][r][lane + off];
                red[1][r][lane] += red[1][r][lane + off];
            }
            __syncthreads();
        }
        if (tid < 8) {
            float m = red[0][tid][0] / DD;
            smean[tid] = m; srstd[tid] = rsqrtf(red[1][tid][0] / DD - m * m + 1e-5f);
        }
        __syncthreads();
    }
    {
        float sgd = sg[d], sbd = sb[d];
        float sc = 1.f + g_ss[b * 2 * DD + d];
        float sh = g_ss[b * 2 * DD + DD + d];
        #pragma unroll
        for (int rr = 0; rr < 8; rr++) {
            float hv = (ay[rr] - smean[rr]) * srstd[rr] * sgd + sbd;
            hv = hv * sc + sh;
            g_act[rowbase + (size_t)rr * DD + d] = hv / (1.f + __expf(-hv));
        }
    }
}

extern "C" void kernel_launch(void* const* d_in, const int* in_sizes, int n_in,
                              void* d_out, int out_size) {
    const float* x   = (const float*)d_in[0];
    const float* xf  = (const float*)d_in[1];
    const float* emb = (const float*)d_in[2];
    const float* ng  = (const float*)d_in[3];
    const float* nb  = (const float*)d_in[4];
    const float* tg  = (const float*)d_in[5];
    const float* tb  = (const float*)d_in[6];
    const float* Wq  = (const float*)d_in[7];
    const float* bq  = (const float*)d_in[8];
    const float* Wk  = (const float*)d_in[9];
    const float* bk  = (const float*)d_in[10];
    const float* Wv  = (const float*)d_in[11];
    const float* bv  = (const float*)d_in[12];
    const float* We  = (const float*)d_in[13];
    const float* be  = (const float*)d_in[14];
    const float* sg  = (const float*)d_in[15];
    const float* sb  = (const float*)d_in[16];
    const float* Wo  = (const float*)d_in[17];
    const float* bo  = (const float*)d_in[18];
    float* out = (float*)d_out;

    k_emb<<<BB, 512>>>(emb, We, be);
    k_cvtW<<<dim3(1024, 3), 256>>>(Wk, Wv, Wq, Wo, bk, bv);
    k_stats<<<BB * NN / 8, 256>>>(xf, LL, 0);
    k_gemm7<0><<<dim3(8, BB * NN / 64), 256>>>(xf, tg, tb, nullptr, nullptr, nullptr);
    k_redk<<<dim3(BB, SPLITS), DD>>>();
    k_comb<<<BB, DD>>>();
    k_stats<<<BB * TT / 8, 256>>>(x, DD, 1);
    k_gemm7<1><<<dim3(4, BB * TT / 64), 256>>>(x, ng, nb, bq, nullptr, nullptr);
    k_attn2<<<dim3(BB * HH, 4), 128>>>();
    k_ascale<<<BB * HH, 256>>>();
    k_smy<<<BB * TT / 8, 512>>>(sg, sb);
    k_gemm7<2><<<dim3(4, BB * TT / 64), 256>>>(nullptr, nullptr, nullptr, bo, x, out);
}